// round 16
// baseline (speedup 1.0000x reference)
#include <cuda_runtime.h>
#include <cuda_fp16.h>

#define FEAT 128
#define NMAX 8192
#define CAP  128            // slots per node bucket (4 sub-buckets x 32)
#define CAP_SHIFT 7
#define WSTRIDE 132         // padded smem row stride (floats) — kills LDS conflicts

// Scratch (__device__ globals; zero-initialized at module load).
__device__ float  g_dis[NMAX];
__device__ float  g_scaled[(size_t)NMAX * FEAT];    // fp32: self-loop term
__device__ __half g_scaledh[(size_t)NMAX * FEAT];   // fp16 mirror: neighbor reads
__device__ int4   g_cnt4[NMAX];                     // 4-way striped counters
__device__ float2 g_edge[(size_t)NMAX * CAP];       // (j bits, w_e)

// ---------------------------------------------------------------------------
// K1: bucket scatter, 2 independent edges per thread (e and e+E/2).
// ---------------------------------------------------------------------------
__global__ void k_scatter(const int* __restrict__ adj0,
                          const int* __restrict__ adj1,
                          const float* __restrict__ ew, int E) {
    int half = E >> 1;
    int t = blockIdx.x * blockDim.x + threadIdx.x;
    if (t >= half) return;
    int e0 = t, e1 = t + half;

    int   i0 = adj0[e0], j0 = adj1[e0];
    int   i1 = adj0[e1], j1 = adj1[e1];
    float w0 = ew[e0],   w1 = ew[e1];

    int sub0 = e0 & 3, sub1 = e1 & 3;
    int p0 = atomicAdd(((int*)&g_cnt4[i0]) + sub0, 1);
    int p1 = atomicAdd(((int*)&g_cnt4[i1]) + sub1, 1);
    g_edge[((size_t)i0 << CAP_SHIFT) + sub0 * 32 + p0] =
        make_float2(__int_as_float(j0), w0);
    g_edge[((size_t)i1 << CAP_SHIFT) + sub1 * 32 + p1] =
        make_float2(__int_as_float(j1), w1);
}

__device__ __forceinline__ unsigned f2tf32(float f) {
    unsigned u;
    asm("cvt.rna.tf32.f32 %0, %1;" : "=r"(u) : "f"(f));
    return u;
}

// ---------------------------------------------------------------------------
// K2: tf32 tensor-core GEMM + dis epilogue (PDL). 256 threads, 64 rows/block.
// Warps 0-3 each compute 16 rows x 128 cols via mma.m16n8k8 (16 k-steps x
// 16 n-tiles); C written back to smem; all 8 warps run the dis epilogue
// (8 rows each) writing fp32 + fp16-mirror scaled rows.
// ---------------------------------------------------------------------------
__global__ void __launch_bounds__(256)
k_gemm(const float* __restrict__ x, const float* __restrict__ w, int n) {
    extern __shared__ float smem[];
    float* Ws = smem;                        // [128][WSTRIDE]
    float* As = smem + FEAT * WSTRIDE;       // [64][WSTRIDE]
    unsigned* Wsu = (unsigned*)Ws;
    unsigned* Asu = (unsigned*)As;

    int tid  = threadIdx.x;
    int lane = tid & 31;
    int wid  = tid >> 5;
    int row0 = blockIdx.x * 64;

    // Stage W (tf32-rounded), padded stride.
    for (int idx = tid; idx < FEAT * FEAT / 4; idx += 256) {
        int r = idx >> 5, c4 = idx & 31;
        float4 v = ((const float4*)w)[idx];
        *(uint4*)&Wsu[r * WSTRIDE + c4 * 4] =
            make_uint4(f2tf32(v.x), f2tf32(v.y), f2tf32(v.z), f2tf32(v.w));
    }
    // Stage A tile (64 rows, tf32-rounded).
    const float4* xg = (const float4*)(x + (size_t)row0 * FEAT);
    for (int idx = tid; idx < 64 * FEAT / 4; idx += 256) {
        int r = idx >> 5, c4 = idx & 31;
        float4 v = xg[idx];
        *(uint4*)&Asu[r * WSTRIDE + c4 * 4] =
            make_uint4(f2tf32(v.x), f2tf32(v.y), f2tf32(v.z), f2tf32(v.w));
    }
    __syncthreads();

    if (wid < 4) {
        int m0 = wid * 16;
        int r = lane >> 2, q = lane & 3;
        float c[16][4];
#pragma unroll
        for (int nt = 0; nt < 16; nt++)
            c[nt][0] = c[nt][1] = c[nt][2] = c[nt][3] = 0.0f;

        for (int ks = 0; ks < 16; ks++) {
            int k0 = ks * 8;
            unsigned a0 = Asu[(m0 + r) * WSTRIDE + k0 + q];
            unsigned a1 = Asu[(m0 + r + 8) * WSTRIDE + k0 + q];
            unsigned a2 = Asu[(m0 + r) * WSTRIDE + k0 + q + 4];
            unsigned a3 = Asu[(m0 + r + 8) * WSTRIDE + k0 + q + 4];
#pragma unroll
            for (int nt = 0; nt < 16; nt++) {
                unsigned b0 = Wsu[(k0 + q) * WSTRIDE + nt * 8 + r];
                unsigned b1 = Wsu[(k0 + q + 4) * WSTRIDE + nt * 8 + r];
                asm volatile(
                    "mma.sync.aligned.m16n8k8.row.col.f32.tf32.tf32.f32 "
                    "{%0,%1,%2,%3}, {%4,%5,%6,%7}, {%8,%9}, {%0,%1,%2,%3};"
                    : "+f"(c[nt][0]), "+f"(c[nt][1]),
                      "+f"(c[nt][2]), "+f"(c[nt][3])
                    : "r"(a0), "r"(a1), "r"(a2), "r"(a3), "r"(b0), "r"(b1));
            }
        }
        // Write C into As (each warp overwrites only its own 16 A rows,
        // which it alone read — no cross-warp hazard).
#pragma unroll
        for (int nt = 0; nt < 16; nt++) {
            int row = m0 + r;
            int col = nt * 8 + q * 2;
            *(float2*)&As[row * WSTRIDE + col]       = make_float2(c[nt][0], c[nt][1]);
            *(float2*)&As[(row + 8) * WSTRIDE + col] = make_float2(c[nt][2], c[nt][3]);
        }
    }
    __syncthreads();

    // Wait for k_scatter's memory (g_cnt4, g_edge) to be visible.
    cudaGridDependencySynchronize();

    // dis epilogue — 8 warps x 8 rows; latency-flat striped reads;
    // dual-precision store of the dis-scaled support row.
#pragma unroll
    for (int rr = 0; rr < 8; rr++) {
        int lrow = wid * 8 + rr;
        int row  = row0 + lrow;
        int4 c4 = g_cnt4[row];
        const float2* b = g_edge + ((size_t)row << CAP_SHIFT);
        float2 e0 = b[lane];
        float2 e1 = b[lane + 32];
        float2 e2 = b[lane + 64];
        float2 e3 = b[lane + 96];
        float s = 0.0f;
        if (lane < c4.x) s += e0.y;
        if (lane < c4.y) s += e1.y;
        if (lane < c4.z) s += e2.y;
        if (lane < c4.w) s += e3.y;
#pragma unroll
        for (int d = 16; d > 0; d >>= 1) s += __shfl_xor_sync(0xffffffffu, s, d);
        float dis = rsqrtf(s + 1.0f + 1e-10f);
        if (lane == 0) g_dis[row] = dis;
        float4 a = *(float4*)&As[lrow * WSTRIDE + lane * 4];
        float4 sc = make_float4(dis * a.x, dis * a.y, dis * a.z, dis * a.w);
        ((float4*)(g_scaled + (size_t)row * FEAT))[lane] = sc;
        __half2 h0 = __floats2half2_rn(sc.x, sc.y);
        __half2 h1 = __floats2half2_rn(sc.z, sc.w);
        uint2 hp = make_uint2(*(unsigned*)&h0, *(unsigned*)&h1);
        ((uint2*)(g_scaledh + (size_t)row * FEAT))[lane] = hp;
    }
}

// ---------------------------------------------------------------------------
// K3: gather. One warp per node i; 128-thread blocks. fp16 neighbor reads,
// 8 forced-in-flight LDG.64 per iteration. Resets g_cnt4[i] for next replay.
// ---------------------------------------------------------------------------
__global__ void __launch_bounds__(128)
k_gather(const float* __restrict__ bias, float* __restrict__ out, int n) {
    __shared__ float2 sh[4][CAP];   // 4 KB
    int warp = threadIdx.x >> 5;
    int lane = threadIdx.x & 31;
    int i = (blockIdx.x * blockDim.x + threadIdx.x) >> 5;
    if (i >= n) return;

    int4 c4 = g_cnt4[i];
    if (lane == 0) g_cnt4[i] = make_int4(0, 0, 0, 0);   // reset for next replay
    const float2* b = g_edge + ((size_t)i << CAP_SHIFT);
    float2 e0 = b[lane];
    float2 e1 = b[lane + 32];
    float2 e2 = b[lane + 64];
    float2 e3 = b[lane + 96];
    int off1 = c4.x, off2 = c4.x + c4.y, off3 = off2 + c4.z;
    int cnt  = off3 + c4.w;
    if (lane < c4.x) sh[warp][lane]        = e0;
    if (lane < c4.y) sh[warp][off1 + lane] = e1;
    if (lane < c4.z) sh[warp][off2 + lane] = e2;
    if (lane < c4.w) sh[warp][off3 + lane] = e3;
    __syncwarp();

    float4 acc = ((const float4*)(g_scaled + (size_t)i * FEAT))[lane];  // self, fp32

    int t = 0;
    for (; t + 8 <= cnt; t += 8) {
        float wgt[8];
        uint2 hv[8];
#pragma unroll
        for (int k = 0; k < 8; k++) {
            float2 e = sh[warp][t + k];
            wgt[k] = e.y;
            const __half* p =
                g_scaledh + (size_t)__float_as_int(e.x) * FEAT + lane * 4;
            asm volatile("ld.global.nc.v2.u32 {%0,%1}, [%2];"
                         : "=r"(hv[k].x), "=r"(hv[k].y) : "l"(p));
        }
#pragma unroll
        for (int k = 0; k < 8; k++) {
            float2 lo = __half22float2(*(__half2*)&hv[k].x);
            float2 hi = __half22float2(*(__half2*)&hv[k].y);
            acc.x += wgt[k] * lo.x; acc.y += wgt[k] * lo.y;
            acc.z += wgt[k] * hi.x; acc.w += wgt[k] * hi.y;
        }
    }
    for (; t < cnt; t++) {
        float2 e = sh[warp][t];
        uint2 hv = ((const uint2*)(g_scaledh + (size_t)__float_as_int(e.x) * FEAT))[lane];
        float2 lo = __half22float2(*(__half2*)&hv.x);
        float2 hi = __half22float2(*(__half2*)&hv.y);
        acc.x += e.y * lo.x; acc.y += e.y * lo.y;
        acc.z += e.y * hi.x; acc.w += e.y * hi.y;
    }

    float dis = g_dis[i];
    float4 bv = ((const float4*)bias)[lane];
    ((float4*)(out + (size_t)i * FEAT))[lane] =
        make_float4(bv.x + dis * acc.x, bv.y + dis * acc.y,
                    bv.z + dis * acc.z, bv.w + dis * acc.w);
}

// ---------------------------------------------------------------------------
extern "C" void kernel_launch(void* const* d_in, const int* in_sizes, int n_in,
                              void* d_out, int out_size) {
    const float* x    = (const float*)d_in[0];
    const int*   adj  = (const int*)d_in[1];     // int32 [2, E]
    const float* ew   = (const float*)d_in[2];
    const float* w    = (const float*)d_in[3];
    const float* bias = (const float*)d_in[4];
    float*       out  = (float*)d_out;

    int n = in_sizes[0] / FEAT;     // 8192
    int E = in_sizes[2];            // 262144

    k_scatter<<<(E / 2 + 255) / 256, 256>>>(adj, adj + E, ew, E);

    // k_gemm with programmatic dependent launch (staging+mma overlap scatter).
    size_t smem_sz = (size_t)(FEAT + 64) * WSTRIDE * sizeof(float);  // ~99 KB
    cudaFuncSetAttribute(k_gemm, cudaFuncAttributeMaxDynamicSharedMemorySize,
                         (int)smem_sz);
    cudaLaunchConfig_t cfg = {};
    cfg.gridDim  = dim3(n / 64);
    cfg.blockDim = dim3(256);
    cfg.dynamicSmemBytes = smem_sz;
    cfg.stream = 0;
    cudaLaunchAttribute attrs[1];
    attrs[0].id = cudaLaunchAttributeProgrammaticStreamSerialization;
    attrs[0].val.programmaticStreamSerializationAllowed = 1;
    cfg.attrs = attrs;
    cfg.numAttrs = 1;
    cudaLaunchKernelEx(&cfg, k_gemm, x, w, n);

    k_gather<<<(n * 32 + 127) / 128, 128>>>(bias, out, n);
}